// round 13
// baseline (speedup 1.0000x reference)
#include <cuda_runtime.h>
#include <cuda_bf16.h>
#include <cstdint>
#include <math.h>

// PolarVoxelizer R13: tan-space angle binning (no atan2f on the hot path).
//   K1 k_zero_tma (primary): cp.async.bulk zeros, 64KB chunks, PDL trigger.
//   K2 k_voxel (secondary, PDL): angle bin via y vs x*tan(a_k) FMA compares
//      (LUT guess + fixup); double-atan2 fallback only within 2e-5 rad of a
//      decision boundary. Register-resident scatter after
//      cudaGridDependencySynchronize().

#define Z_DEPTH   100
#define HALF_FOV  1.134f
#define R_MIN_C   2.7f
#define R_MAX_C   165.0f
#define SLOPE_REJ 2.2f        // atan(2.2)=1.1441 > HALF_FOV + any fp slop
#define MAX_RB    512
#define MAX_AB    256
#define ZCHUNK    65536       // bytes per bulk copy (= smem buffer size)
#define LUT_N     128
#define T_LO      (-2.2f)
#define T_RANGE   4.4f
#define NEAR_EPS  2.0e-5f     // angle-space margin for exact-fallback

// Exact searchsorted(side='left') given an approximate starting index.
__device__ __forceinline__ int lb_fixup(const float* __restrict__ a, int n, float v, int idx) {
    idx = min(max(idx, 0), n);
    while (idx > 0 && a[idx - 1] >= v) --idx;
    while (idx < n && a[idx] < v) ++idx;
    return idx;
}

__global__ __launch_bounds__(128) void k_zero_tma(char* __restrict__ out,
                                                  long long total_bytes)
{
#if __CUDA_ARCH__ >= 900
    cudaTriggerProgrammaticLaunchCompletion();   // let k_voxel co-schedule now
#endif
    __shared__ __align__(128) float4 buf[ZCHUNK / 16];   // 64 KB of zeros

    for (int i = threadIdx.x; i < ZCHUNK / 16; i += blockDim.x)
        buf[i] = make_float4(0.f, 0.f, 0.f, 0.f);
    __syncthreads();
    asm volatile("fence.proxy.async.shared::cta;" ::: "memory");

    if (threadIdx.x == 0) {
        unsigned int saddr;
        asm("{ .reg .u64 t; cvta.to.shared.u64 t, %1; cvt.u32.u64 %0, t; }"
            : "=r"(saddr) : "l"(buf));

        long long nfull = total_bytes / ZCHUNK;
        for (long long c = blockIdx.x; c < nfull; c += gridDim.x) {
            char* g = out + c * (long long)ZCHUNK;
            asm volatile(
                "cp.async.bulk.global.shared::cta.bulk_group [%0], [%1], %2;"
                :: "l"(g), "r"(saddr), "r"((unsigned)ZCHUNK) : "memory");
        }
        long long rem = total_bytes - nfull * ZCHUNK;
        if (blockIdx.x == 0 && rem >= 16) {
            char* g = out + nfull * (long long)ZCHUNK;
            asm volatile(
                "cp.async.bulk.global.shared::cta.bulk_group [%0], [%1], %2;"
                :: "l"(g), "r"(saddr), "r"((unsigned)(rem & ~15LL)) : "memory");
        }
        asm volatile("cp.async.bulk.commit_group;" ::: "memory");
        asm volatile("cp.async.bulk.wait_group 0;" ::: "memory");
    }
}

__global__ __launch_bounds__(256, 5) void k_voxel(
    const float4* __restrict__ lidars4,
    const float* __restrict__ r_bins,
    const float* __restrict__ angle_bins,
    float* __restrict__ out,
    int npts, int num_r, int num_a,
    unsigned long long div_magic,          // exact i/n_per_s via (i*magic)>>40
    float log2_rmin, float inv_log2_1pd)   // radius geometric-grid guess params
{
    __shared__ float s_r[MAX_RB];
    __shared__ float s_a[MAX_AB];
    __shared__ float s_t[MAX_AB];          // tan(angle_bins)
    __shared__ short s_lut[LUT_N];         // t-slot -> bin guess
    for (int i = threadIdx.x; i < num_r; i += blockDim.x) s_r[i] = r_bins[i];
    for (int i = threadIdx.x; i < num_a; i += blockDim.x) s_a[i] = angle_bins[i];
    __syncthreads();
    for (int i = threadIdx.x; i < num_a; i += blockDim.x) s_t[i] = tanf(s_a[i]);
    __syncthreads();
    for (int j = threadIdx.x; j < LUT_N; j += blockDim.x) {
        float tc = T_LO + (j + 0.5f) * (T_RANGE / LUT_N);
        int lo = 0, hi = num_a;
        while (lo < hi) { int m = (lo + hi) >> 1; if (s_t[m] < tc) lo = m + 1; else hi = m; }
        s_lut[j] = (short)lo;
    }
    __syncthreads();

    const int c = blockIdx.x * blockDim.x + threadIdx.x;   // chunk of 4 points
    const int nchunks = (npts + 3) >> 2;

    int lins[4] = {-1, -1, -1, -1};

    if (c < nchunks) {
        int base = c * 4;
        int v4 = c * 3;
        float4 q0 = lidars4[v4 + 0];
        float4 q1 = lidars4[v4 + 1];
        float4 q2 = lidars4[v4 + 2];
        float px[4] = {q0.x, q0.w, q1.z, q2.y};
        float py[4] = {q0.y, q1.x, q1.w, q2.z};
        float pz[4] = {q0.z, q1.y, q2.x, q2.w};

        #pragma unroll
        for (int k = 0; k < 4; ++k) {
            int i = base + k;
            float x = px[k], y = py[k], z = pz[k];

            // geometric pre-rejection: provably outside FOV (|angle| > 1.1441)
            if (i < npts && x > 0.0f && fabsf(y) <= SLOPE_REJ * x) {
                // radius: bit-exact vs XLA f32 (no FMA contraction, IEEE sqrt)
                float radius = __fsqrt_rn(__fadd_rn(__fmul_rn(x, x), __fmul_rn(y, y)));
                if ((radius < R_MAX_C) && (radius > R_MIN_C)) {
                    // ---- angle bin in tan-space: y vs x*tan(a_k), x>0 ----
                    float t = __fdividef(y, x);   // guess only
                    int gj = (int)((t - T_LO) * (LUT_N / T_RANGE));
                    gj = min(max(gj, 0), LUT_N - 1);
                    int yg = s_lut[gj];
                    while (yg > 0      && __fmaf_rn(x, s_t[yg - 1], -y) >= 0.f) --yg;
                    while (yg < num_a && __fmaf_rn(x, s_t[yg], -y) < 0.f) ++yg;

                    // near any decision boundary? (bin edges + FOV endpoints)
                    float xm = x * NEAR_EPS;
                    bool near = false;
                    if (yg < num_a) { float tk = s_t[yg];
                        near |= fabsf(__fmaf_rn(x, tk, -y)) <= xm * __fmaf_rn(tk, tk, 1.f); }
                    if (yg > 0)     { float tk = s_t[yg - 1];
                        near |= fabsf(__fmaf_rn(x, tk, -y)) <= xm * __fmaf_rn(tk, tk, 1.f); }
                    { float tk = s_t[0];
                        near |= fabsf(__fmaf_rn(x, tk, -y)) <= xm * __fmaf_rn(tk, tk, 1.f); }
                    { float tk = s_t[num_a - 1];
                        near |= fabsf(__fmaf_rn(x, tk, -y)) <= xm * __fmaf_rn(tk, tk, 1.f); }

                    bool valid;
                    if (near) {
                        // exact fallback: correctly-rounded f32 atan2, angle-space search
                        float v = (float)atan2((double)y, (double)x);
                        yg = lb_fixup(s_a, num_a, v, yg);
                        valid = fabsf(v) < HALF_FOV;
                    } else {
                        // strict FOV: y > x*t_0  &&  y < x*t_last
                        valid = (__fmaf_rn(x, s_t[0], -y) < 0.f) &&
                                (__fmaf_rn(x, s_t[num_a - 1], -y) > 0.f);
                    }

                    if (valid) {
                        int xg0 = (int)floorf((__log2f(radius) - log2_rmin) * inv_log2_1pd);
                        int xg = lb_fixup(s_r, num_r, radius, xg0);
                        int zg = (int)floorf(__fdiv_rn(__fsub_rn(z, -2.0f), 0.2f));
                        int s = (int)(((unsigned long long)i * div_magic) >> 40);
                        lins[k] = ((s * Z_DEPTH + zg) * num_a + yg) * num_r + xg;
                    }
                }
            }
        }
    }

#if __CUDA_ARCH__ >= 900
    cudaGridDependencySynchronize();   // wait for k_zero_tma completion + visibility
#endif

    #pragma unroll
    for (int k = 0; k < 4; ++k)
        if (lins[k] >= 0) out[lins[k]] = 1.0f;
}

extern "C" void kernel_launch(void* const* d_in, const int* in_sizes, int n_in,
                              void* d_out, int out_size) {
    const float* lidars     = (const float*)d_in[0];
    const float* r_bins     = (const float*)d_in[1];
    const float* angle_bins = (const float*)d_in[2];
    float* out = (float*)d_out;

    const int B = 2;  // output keeps only batch 0
    int num_r = in_sizes[1];
    int num_a = in_sizes[2];
    int npts  = in_sizes[0] / (3 * B);
    int S     = out_size / (Z_DEPTH * num_a * num_r);
    int n_per_s = npts / S;

    // radius geometric-grid guess params (guess only; exactness via lb_fixup)
    double delta = pow((165.0 + 0.0001) / 2.7, 1.0 / (double)(num_r - 1)) - 1.0;
    float log2_rmin = (float)(log(2.7) / log(2.0));
    float inv_log2_1pd = (float)(log(2.0) / log(1.0 + delta));

    // Exact floor(i / n_per_s) for i < 2^20: magic = ceil(2^40 / n_per_s)
    unsigned long long div_magic =
        ((1ULL << 40) + (unsigned long long)n_per_s - 1ULL) / (unsigned long long)n_per_s;

    int sms = 148;
    cudaDeviceGetAttribute(&sms, cudaDevAttrMultiProcessorCount, 0);

    // --- K1 (primary): TMA zero of the output; triggers PDL at entry ---
    k_zero_tma<<<sms, 128>>>((char*)out, (long long)out_size * 4);

    // --- K2 (secondary, PDL): 1 chunk/thread, 5 blocks/SM, single wave ---
    {
        int nchunks = (npts + 3) / 4;
        int v_blocks = (nchunks + 255) / 256;
        cudaLaunchConfig_t cfg = {};
        cfg.gridDim = dim3(v_blocks, 1, 1);
        cfg.blockDim = dim3(256, 1, 1);
        cfg.dynamicSmemBytes = 0;
        cfg.stream = 0;
        cudaLaunchAttribute attr[1];
        attr[0].id = cudaLaunchAttributeProgrammaticStreamSerialization;
        attr[0].val.programmaticStreamSerializationAllowed = 1;
        cfg.attrs = attr;
        cfg.numAttrs = 1;
        cudaLaunchKernelEx(&cfg, k_voxel,
            (const float4*)lidars, r_bins, angle_bins, out,
            npts, num_r, num_a, div_magic,
            log2_rmin, inv_log2_1pd);
    }
}